// round 2
// baseline (speedup 1.0000x reference)
#include <cuda_runtime.h>
#include <math.h>

#define BB   8
#define NN   2048
#define DIN  256
#define DV   256
#define HH   8
#define HDD  32
#define DFF  512
#define MROWS (BB*NN)   // 16384

// ---------------- scratch (static device memory; no allocations) ----------------
__device__ float g_xn[MROWS*DIN];
__device__ float g_Q [MROWS*DV];
__device__ float g_K [MROWS*DV];   // [B,H,N,HD]
__device__ float g_V [MROWS*DV];   // [B,H,N,HD]
__device__ float g_O [MROWS*DV];
__device__ float g_On[MROWS*DV];
__device__ float g_H1[MROWS*DFF];

// ---------------- layernorm over D=256, one block per row ----------------
__global__ __launch_bounds__(256)
void ln_kernel(const float* __restrict__ src, float* __restrict__ dst,
               const float* __restrict__ gamma, const float* __restrict__ beta)
{
    int row = blockIdx.x;
    int tid = threadIdx.x;
    float v = src[row*256 + tid];
    float s = v, s2 = v*v;
    #pragma unroll
    for (int o = 16; o; o >>= 1) {
        s  += __shfl_xor_sync(0xffffffffu, s,  o);
        s2 += __shfl_xor_sync(0xffffffffu, s2, o);
    }
    __shared__ float ws[8], ws2[8];
    int w = tid >> 5, ln = tid & 31;
    if (ln == 0) { ws[w] = s; ws2[w] = s2; }
    __syncthreads();
    if (w == 0) {
        float a  = (ln < 8) ? ws[ln]  : 0.f;
        float b  = (ln < 8) ? ws2[ln] : 0.f;
        #pragma unroll
        for (int o = 4; o; o >>= 1) {
            a += __shfl_xor_sync(0xffffffffu, a, o);
            b += __shfl_xor_sync(0xffffffffu, b, o);
        }
        if (ln == 0) { ws[0] = a; ws2[0] = b; }
    }
    __syncthreads();
    float mu  = ws[0]  * (1.f/256.f);
    float var = ws2[0] * (1.f/256.f) - mu*mu;
    float inv = rsqrtf(var + 1e-5f);
    dst[row*256 + tid] = (v - mu) * inv * gamma[tid] + beta[tid];
}

// ---------------- tiled SGEMM: C[M x NDIM] = A[M x KDIM] @ W[KDIM x NDIM] ----------------
// BM=BN=64, BK=16, 256 threads, 4x4 microtile per thread.
// MODE 0: out = acc + bias                        (row-major [M,NDIM])
// MODE 1: scatter to [B,H,N,HD] with bias         (for K, V)
// MODE 2: out = gelu(acc + bias)                  (exact gelu, erf)
// MODE 3: out = resid + acc + bias                (final output)
template<int KDIM, int NDIM, int MODE>
__global__ __launch_bounds__(256)
void gemm_kernel(const float* __restrict__ A, const float* __restrict__ W,
                 const float* __restrict__ bias, float* __restrict__ out,
                 const float* __restrict__ resid)
{
    __shared__ float As[64][17];
    __shared__ float Bs[16][64];
    const int tid = threadIdx.x;
    const int tx = tid & 15, ty = tid >> 4;
    const int rowBase = blockIdx.y * 64;
    const int colBase = blockIdx.x * 64;

    float acc[4][4];
    #pragma unroll
    for (int i = 0; i < 4; i++)
        #pragma unroll
        for (int j = 0; j < 4; j++) acc[i][j] = 0.f;

    const int ar = tid >> 2, ac4 = tid & 3;   // A tile: 64 rows x 4 float4
    const int br = tid >> 4, bc4 = tid & 15;  // B tile: 16 rows x 16 float4

    #pragma unroll 1
    for (int kt = 0; kt < KDIM/16; kt++) {
        float4 a4 = *(const float4*)&A[(rowBase + ar)*KDIM + kt*16 + ac4*4];
        As[ar][ac4*4+0] = a4.x; As[ar][ac4*4+1] = a4.y;
        As[ar][ac4*4+2] = a4.z; As[ar][ac4*4+3] = a4.w;
        *(float4*)&Bs[br][bc4*4] =
            *(const float4*)&W[(kt*16 + br)*NDIM + colBase + bc4*4];
        __syncthreads();
        #pragma unroll
        for (int kk = 0; kk < 16; kk++) {
            float4 b4 = *(const float4*)&Bs[kk][tx*4];
            float av[4];
            #pragma unroll
            for (int i = 0; i < 4; i++) av[i] = As[ty*4+i][kk];
            #pragma unroll
            for (int i = 0; i < 4; i++) {
                acc[i][0] += av[i]*b4.x;
                acc[i][1] += av[i]*b4.y;
                acc[i][2] += av[i]*b4.z;
                acc[i][3] += av[i]*b4.w;
            }
        }
        __syncthreads();
    }

    #pragma unroll
    for (int i = 0; i < 4; i++) {
        int r  = rowBase + ty*4 + i;
        int c0 = colBase + tx*4;
        if (MODE == 0) {
            float4 o;
            o.x = acc[i][0] + bias[c0+0];
            o.y = acc[i][1] + bias[c0+1];
            o.z = acc[i][2] + bias[c0+2];
            o.w = acc[i][3] + bias[c0+3];
            *(float4*)&out[r*NDIM + c0] = o;
        } else if (MODE == 1) {
            int b = r >> 11, n = r & (NN-1);
            #pragma unroll
            for (int j = 0; j < 4; j++) {
                int c = c0 + j;
                int h = c >> 5, d = c & 31;
                out[((b*HH + h)*NN + n)*HDD + d] = acc[i][j] + bias[c];
            }
        } else if (MODE == 2) {
            float4 o;
            #pragma unroll
            for (int j = 0; j < 4; j++) {
                float v = acc[i][j] + bias[c0+j];
                float g = 0.5f * v * (1.f + erff(v * 0.70710678118654752f));
                ((float*)&o)[j] = g;
            }
            *(float4*)&out[r*NDIM + c0] = o;
        } else {
            float4 rr = *(const float4*)&resid[r*256 + c0];
            float4 o;
            o.x = rr.x + acc[i][0] + bias[c0+0];
            o.y = rr.y + acc[i][1] + bias[c0+1];
            o.z = rr.z + acc[i][2] + bias[c0+2];
            o.w = rr.w + acc[i][3] + bias[c0+3];
            *(float4*)&out[r*256 + c0] = o;
        }
    }
}

// ---------------- fused flash attention + per-head Q residual ----------------
// grid: (N/128, B*H). block: 256 threads.
// Each block: one (b,h), 128 query rows. Online softmax over 64 k-tiles of 32.
// Thread (ry=tid/8, cx=tid%8): S rows ry*4..+3, S cols cx*4..+3 (tile width 32);
// AV acc rows ry*4..+3, output cols cx*4..+3.
__global__ __launch_bounds__(256)
void attn_kernel(const float* __restrict__ Q, const float* __restrict__ K,
                 const float* __restrict__ V, float* __restrict__ O)
{
    __shared__ float Qs[128][33];
    __shared__ float Ks[32][33];
    __shared__ float Vs[32][32];
    __shared__ float Ps[128][33];

    const int bh = blockIdx.y;           // 0..63
    const int b  = bh >> 3, h = bh & 7;
    const int qbase = blockIdx.x * 128;
    const int tid = threadIdx.x;
    const int ry = tid >> 3;             // 0..31
    const int cx = tid & 7;              // 0..7

    // load Q tile [128 x 32]
    #pragma unroll
    for (int it = 0; it < 4; it++) {
        int idx = tid + it*256;
        int r = idx >> 3, c4 = idx & 7;
        float4 q4 = *(const float4*)&Q[(b*NN + qbase + r)*DV + h*HDD + c4*4];
        Qs[r][c4*4+0] = q4.x; Qs[r][c4*4+1] = q4.y;
        Qs[r][c4*4+2] = q4.z; Qs[r][c4*4+3] = q4.w;
    }

    float m[4], l[4], acc[4][4];
    #pragma unroll
    for (int i = 0; i < 4; i++) {
        m[i] = -INFINITY; l[i] = 0.f;
        #pragma unroll
        for (int j = 0; j < 4; j++) acc[i][j] = 0.f;
    }

    const float* Kb = K + bh*NN*HDD;
    const float* Vb = V + bh*NN*HDD;

    #pragma unroll 1
    for (int kt = 0; kt < NN/32; kt++) {
        __syncthreads();   // previous AV done before overwriting Ks/Vs
        {
            int r = tid >> 3, c4 = tid & 7;   // 32 rows x 8 float4
            float4 k4 = *(const float4*)&Kb[(kt*32 + r)*HDD + c4*4];
            Ks[r][c4*4+0] = k4.x; Ks[r][c4*4+1] = k4.y;
            Ks[r][c4*4+2] = k4.z; Ks[r][c4*4+3] = k4.w;
            float4 v4 = *(const float4*)&Vb[(kt*32 + r)*HDD + c4*4];
            *(float4*)&Vs[r][c4*4] = v4;
        }
        __syncthreads();

        // S = Q K^T (tile 128x32), scale 1/sqrt(256)
        float s[4][4];
        #pragma unroll
        for (int i = 0; i < 4; i++)
            #pragma unroll
            for (int j = 0; j < 4; j++) s[i][j] = 0.f;
        #pragma unroll
        for (int d = 0; d < 32; d++) {
            float qa[4], kb[4];
            #pragma unroll
            for (int i = 0; i < 4; i++) qa[i] = Qs[ry*4+i][d];
            #pragma unroll
            for (int j = 0; j < 4; j++) kb[j] = Ks[cx*4+j][d];
            #pragma unroll
            for (int i = 0; i < 4; i++)
                #pragma unroll
                for (int j = 0; j < 4; j++) s[i][j] += qa[i]*kb[j];
        }

        // online softmax per row (8 lanes per row share via shfl)
        #pragma unroll
        for (int i = 0; i < 4; i++) {
            #pragma unroll
            for (int j = 0; j < 4; j++) s[i][j] *= 0.0625f;
            float rm = fmaxf(fmaxf(s[i][0], s[i][1]), fmaxf(s[i][2], s[i][3]));
            #pragma unroll
            for (int o = 1; o < 8; o <<= 1)
                rm = fmaxf(rm, __shfl_xor_sync(0xffffffffu, rm, o));
            float nm = fmaxf(m[i], rm);
            float sc = __expf(m[i] - nm);
            float rs = 0.f;
            #pragma unroll
            for (int j = 0; j < 4; j++) {
                s[i][j] = __expf(s[i][j] - nm);
                rs += s[i][j];
            }
            #pragma unroll
            for (int o = 1; o < 8; o <<= 1)
                rs += __shfl_xor_sync(0xffffffffu, rs, o);
            l[i] = l[i]*sc + rs;
            m[i] = nm;
            #pragma unroll
            for (int j = 0; j < 4; j++) acc[i][j] *= sc;
            #pragma unroll
            for (int j = 0; j < 4; j++) Ps[ry*4+i][cx*4+j] = s[i][j];
        }
        __syncthreads();

        // acc += P @ V  (thread owns rows ry*4..+3, cols cx*4..+3)
        #pragma unroll
        for (int k = 0; k < 32; k++) {
            float4 v4 = *(const float4*)&Vs[k][cx*4];
            #pragma unroll
            for (int i = 0; i < 4; i++) {
                float p = Ps[ry*4+i][k];
                acc[i][0] += p*v4.x;
                acc[i][1] += p*v4.y;
                acc[i][2] += p*v4.z;
                acc[i][3] += p*v4.w;
            }
        }
    }

    // epilogue: O = Q + softmax(S) V
    #pragma unroll
    for (int i = 0; i < 4; i++) {
        int r = ry*4 + i;
        float inv = 1.f / l[i];
        float4 o;
        o.x = Qs[r][cx*4+0] + acc[i][0]*inv;
        o.y = Qs[r][cx*4+1] + acc[i][1]*inv;
        o.z = Qs[r][cx*4+2] + acc[i][2]*inv;
        o.w = Qs[r][cx*4+3] + acc[i][3]*inv;
        *(float4*)&O[(b*NN + qbase + r)*DV + h*HDD + cx*4] = o;
    }
}

// ---------------- launch ----------------
extern "C" void kernel_launch(void* const* d_in, const int* /*in_sizes*/, int /*n_in*/,
                              void* d_out, int /*out_size*/)
{
    const float* x     = (const float*)d_in[0];
    const float* y     = (const float*)d_in[1];
    const float* Wq    = (const float*)d_in[2];
    const float* bq    = (const float*)d_in[3];
    const float* Wk    = (const float*)d_in[4];
    const float* bk    = (const float*)d_in[5];
    const float* Wv    = (const float*)d_in[6];
    const float* bv    = (const float*)d_in[7];
    const float* W1    = (const float*)d_in[8];
    const float* b1    = (const float*)d_in[9];
    const float* W2    = (const float*)d_in[10];
    const float* b2    = (const float*)d_in[11];
    const float* ln0_g = (const float*)d_in[12];
    const float* ln0_b = (const float*)d_in[13];
    const float* ln1_g = (const float*)d_in[14];
    const float* ln1_b = (const float*)d_in[15];
    float* out = (float*)d_out;

    float *xn, *Q, *K, *V, *O, *On, *H1;
    cudaGetSymbolAddress((void**)&xn, g_xn);
    cudaGetSymbolAddress((void**)&Q,  g_Q);
    cudaGetSymbolAddress((void**)&K,  g_K);
    cudaGetSymbolAddress((void**)&V,  g_V);
    cudaGetSymbolAddress((void**)&O,  g_O);
    cudaGetSymbolAddress((void**)&On, g_On);
    cudaGetSymbolAddress((void**)&H1, g_H1);

    ln_kernel<<<MROWS, 256>>>(x, xn, ln0_g, ln0_b);
    gemm_kernel<256,256,0><<<dim3(4,  MROWS/64), 256>>>(xn, Wq, bq, Q,  nullptr);
    gemm_kernel<256,256,1><<<dim3(4,  MROWS/64), 256>>>(y,  Wk, bk, K,  nullptr);
    gemm_kernel<256,256,1><<<dim3(4,  MROWS/64), 256>>>(y,  Wv, bv, V,  nullptr);
    attn_kernel<<<dim3(NN/128, BB*HH), 256>>>(Q, K, V, O);
    ln_kernel<<<MROWS, 256>>>(O, On, ln1_g, ln1_b);
    gemm_kernel<256,512,2><<<dim3(8,  MROWS/64), 256>>>(On, W1, b1, H1, nullptr);
    gemm_kernel<512,256,3><<<dim3(4,  MROWS/64), 256>>>(H1, W2, b2, out, O);
}